// round 2
// baseline (speedup 1.0000x reference)
#include <cuda_runtime.h>
#include <cfloat>

// Problem constants (fixed by reference: HIDDEN=128, NUM_HEADS=8)
constexpr int DH  = 16;    // head dim
constexpr int NH  = 8;     // heads
constexpr int HID = 128;   // hidden
constexpr int BQ  = 128;   // queries per block (1 thread per query)
constexpr int TK  = 128;   // key tile staged in smem
constexpr int KU  = 8;     // key unroll inside tile

// Single-instruction MUFU EX2 (exp2), independent of --use_fast_math.
__device__ __forceinline__ float fast_exp2(float x) {
    float r;
    asm("ex2.approx.ftz.f32 %0, %1;" : "=f"(r) : "f"(x));
    return r;
}

__global__ __launch_bounds__(BQ) void mha_fp32_kernel(
    const float* __restrict__ kv,     // [B, S, 2*HID]  (first HID = K, second = V)
    const float* __restrict__ qg,     // [B, S, HID]
    const int*   __restrict__ slen,   // [B]
    float*       __restrict__ out,    // [B, S, HID]
    int S)
{
    __shared__ float Ks[TK * DH];
    __shared__ float Vs[TK * DH];

    const int b  = blockIdx.z;
    const int h  = blockIdx.y;
    const int qi = blockIdx.x * BQ + threadIdx.x;
    const int n  = slen[b];

    // Fold sqrt(d_head)=4 (reference MULTIPLIES by sqrt) and log2(e) into q,
    // so softmax runs in exp2 domain: one MUFU per key.
    const float scale = 4.0f * 1.4426950408889634f;

    float q[DH];
    {
        const float4* qp = reinterpret_cast<const float4*>(
            qg + ((size_t)b * S + qi) * HID + h * DH);
#pragma unroll
        for (int g = 0; g < 4; g++) {
            float4 t = qp[g];
            q[4*g+0] = t.x * scale;
            q[4*g+1] = t.y * scale;
            q[4*g+2] = t.z * scale;
            q[4*g+3] = t.w * scale;
        }
    }

    float acc[DH];
#pragma unroll
    for (int d = 0; d < DH; d++) acc[d] = 0.0f;
    float m = -FLT_MAX;
    float l = 0.0f;

    const float* kbase = kv + ((size_t)b * S) * (2 * HID) + h * DH;

    const int row = threadIdx.x >> 2;   // 0..31
    const int seg = threadIdx.x & 3;    // 0..3  (16B segment within 64B row)

    const int ntiles = (n + TK - 1) / TK;   // skip fully-masked tiles
    for (int tile = 0; tile < ntiles; tile++) {
        const int t0 = tile * TK;
        const int tn = min(TK, n - t0);

        __syncthreads();
        // Stage K/V tile: warp covers 8 rows x 4 segments, conflict-free STS.128.
#pragma unroll
        for (int r = 0; r < TK; r += 32) {
            int rr = row + r;
            float4 kval = make_float4(0.f, 0.f, 0.f, 0.f);
            float4 vval = make_float4(0.f, 0.f, 0.f, 0.f);
            if (rr < tn) {
                const float* src = kbase + (size_t)(t0 + rr) * (2 * HID) + seg * 4;
                kval = *reinterpret_cast<const float4*>(src);
                vval = *reinterpret_cast<const float4*>(src + HID);
            }
            *reinterpret_cast<float4*>(Ks + rr * DH + seg * 4) = kval;
            *reinterpret_cast<float4*>(Vs + rr * DH + seg * 4) = vval;
        }
        __syncthreads();

        for (int k0 = 0; k0 < tn; k0 += KU) {
            float s[KU];
#pragma unroll
            for (int kk = 0; kk < KU; kk++) {
                const float4* kr = reinterpret_cast<const float4*>(Ks + (k0 + kk) * DH);
                float4 A = kr[0], Bv = kr[1], C = kr[2], D = kr[3];
                float d0 = q[0]  * A.x  + q[1]  * A.y;
                float d1 = q[2]  * A.z  + q[3]  * A.w;
                float d2 = q[4]  * Bv.x + q[5]  * Bv.y;
                float d3 = q[6]  * Bv.z + q[7]  * Bv.w;
                float d4 = q[8]  * C.x  + q[9]  * C.y;
                float d5 = q[10] * C.z  + q[11] * C.w;
                float d6 = q[12] * D.x  + q[13] * D.y;
                float d7 = q[14] * D.z  + q[15] * D.w;
                float sv = ((d0 + d1) + (d2 + d3)) + ((d4 + d5) + (d6 + d7));
                // mask keys beyond seq_len (covers partial-tile zero rows too)
                s[kk] = (t0 + k0 + kk < n) ? sv : -FLT_MAX;
            }

            float cm = s[0];
#pragma unroll
            for (int kk = 1; kk < KU; kk++) cm = fmaxf(cm, s[kk]);
            const float mnew = fmaxf(m, cm);
            const float corr = fast_exp2(m - mnew);   // first chunk: exp2(-huge) = 0, safe
            m = mnew;
            l *= corr;
#pragma unroll
            for (int d = 0; d < DH; d++) acc[d] *= corr;

            float p[KU];
#pragma unroll
            for (int kk = 0; kk < KU; kk++) {
                p[kk] = fast_exp2(s[kk] - mnew);      // masked -> exp2(-huge) = 0
                l += p[kk];
            }

#pragma unroll
            for (int kk = 0; kk < KU; kk++) {
                const float4* vr = reinterpret_cast<const float4*>(Vs + (k0 + kk) * DH);
                float4 A = vr[0], Bv = vr[1], C = vr[2], D = vr[3];
                acc[0]  = fmaf(p[kk], A.x,  acc[0]);
                acc[1]  = fmaf(p[kk], A.y,  acc[1]);
                acc[2]  = fmaf(p[kk], A.z,  acc[2]);
                acc[3]  = fmaf(p[kk], A.w,  acc[3]);
                acc[4]  = fmaf(p[kk], Bv.x, acc[4]);
                acc[5]  = fmaf(p[kk], Bv.y, acc[5]);
                acc[6]  = fmaf(p[kk], Bv.z, acc[6]);
                acc[7]  = fmaf(p[kk], Bv.w, acc[7]);
                acc[8]  = fmaf(p[kk], C.x,  acc[8]);
                acc[9]  = fmaf(p[kk], C.y,  acc[9]);
                acc[10] = fmaf(p[kk], C.z,  acc[10]);
                acc[11] = fmaf(p[kk], C.w,  acc[11]);
                acc[12] = fmaf(p[kk], D.x,  acc[12]);
                acc[13] = fmaf(p[kk], D.y,  acc[13]);
                acc[14] = fmaf(p[kk], D.z,  acc[14]);
                acc[15] = fmaf(p[kk], D.w,  acc[15]);
            }
        }
    }

    const float inv = 1.0f / l;   // l > 0: seq_len >= 1 guarantees a valid key
    float* op = out + ((size_t)b * S + qi) * HID + h * DH;
#pragma unroll
    for (int g = 0; g < 4; g++) {
        float4 o = make_float4(acc[4*g] * inv, acc[4*g+1] * inv,
                               acc[4*g+2] * inv, acc[4*g+3] * inv);
        reinterpret_cast<float4*>(op)[g] = o;
    }
}

extern "C" void kernel_launch(void* const* d_in, const int* in_sizes, int n_in,
                              void* d_out, int out_size)
{
    const float* kv = (const float*)d_in[0];   // key_and_value [B,S,256]
    const float* qg = (const float*)d_in[1];   // query         [B,S,128]
    const int*   sl = (const int*)  d_in[2];   // seq_len       [B,1]

    const int B = in_sizes[2];                       // [B,1] ints
    const int S = in_sizes[1] / (B * HID);           // queries per batch

    dim3 grid(S / BQ, NH, B);
    mha_fp32_kernel<<<grid, BQ>>>(kv, qg, sl, (float*)d_out, S);
}

// round 5
// speedup vs baseline: 1.2303x; 1.2303x over previous
#include <cuda_runtime.h>
#include <cfloat>

// Problem constants (fixed by reference: HIDDEN=128, NUM_HEADS=8)
constexpr int DH   = 16;    // head dim
constexpr int NH   = 8;     // heads
constexpr int HID  = 128;   // hidden
constexpr int TPB  = 128;   // threads per block
constexpr int QT   = 2;     // queries per thread
constexpr int QBLK = TPB * QT;  // 256 queries per block
constexpr int TK   = 128;   // key tile staged in smem
constexpr int KU   = 4;     // key unroll inside tile
constexpr int NSPLIT = 2;   // key-range splits (flash split-K)

// Dataset-fixed max shapes (B=4, S=2048) for static scratch.
constexpr int MAXB = 4;
constexpr int MAXS = 2048;
constexpr int BNS  = MAXB * NH * MAXS;

// Split-K partials: m (log2-domain running max), l (running denom),
// unnormalized accumulator o ([split][b][h][g][q] float4 groups, coalesced on q).
__device__ float  g_m[NSPLIT * BNS];
__device__ float  g_l[NSPLIT * BNS];
__device__ float4 g_o[NSPLIT * MAXB * NH * 4 * MAXS];

typedef unsigned long long ull;

__device__ __forceinline__ float fast_exp2(float x) {
    float r; asm("ex2.approx.ftz.f32 %0, %1;" : "=f"(r) : "f"(x)); return r;
}
__device__ __forceinline__ ull pack2(float lo, float hi) {
    ull r; asm("mov.b64 %0, {%1, %2};" : "=l"(r) : "f"(lo), "f"(hi)); return r;
}
__device__ __forceinline__ void unpack2(ull v, float& lo, float& hi) {
    asm("mov.b64 {%0, %1}, %2;" : "=f"(lo), "=f"(hi) : "l"(v));
}
// Packed 2x fp32 ops (PTX ISA 8.6, sm_100+; IEEE rn per lane)
__device__ __forceinline__ ull ffma2(ull a, ull b, ull c) {
    ull r; asm("fma.rn.f32x2 %0, %1, %2, %3;" : "=l"(r) : "l"(a), "l"(b), "l"(c)); return r;
}
__device__ __forceinline__ ull fmul2(ull a, ull b) {
    ull r; asm("mul.rn.f32x2 %0, %1, %2;" : "=l"(r) : "l"(a), "l"(b)); return r;
}
__device__ __forceinline__ ull fadd2(ull a, ull b) {
    ull r; asm("add.rn.f32x2 %0, %1, %2;" : "=l"(r) : "l"(a), "l"(b)); return r;
}

__global__ __launch_bounds__(TPB) void mha_main_kernel(
    const float* __restrict__ kv,     // [B, S, 2*HID]
    const float* __restrict__ qg,     // [B, S, HID]
    const int*   __restrict__ slen,   // [B]
    int S)
{
    __shared__ float Ks[TK * DH];
    __shared__ float Vs[TK * DH];

    const int b  = blockIdx.z;
    const int h  = blockIdx.y;
    const int qb = blockIdx.x / NSPLIT;
    const int sp = blockIdx.x % NSPLIT;
    const int n  = slen[b];

    // Balanced key range for this split: half = ceil(n/NSPLIT)
    const int half  = (n + NSPLIT - 1) / NSPLIT;
    const int start = sp * half;
    const int end   = min(n, start + half);

    const int tid = threadIdx.x;
    const int q0  = qb * QBLK + tid;          // query 0; query 1 = q0 + TPB

    // Fold sqrt(d_head)=4 (reference MULTIPLIES by sqrt) and log2(e) into q.
    const float scale = 4.0f * 1.4426950408889634f;

    // Packed q for both queries: qp[j][i] = (q[2i], q[2i+1])
    ull qp[QT][8];
#pragma unroll
    for (int j = 0; j < QT; j++) {
        const float4* qptr = reinterpret_cast<const float4*>(
            qg + ((size_t)b * S + (q0 + j * TPB)) * HID + h * DH);
#pragma unroll
        for (int g = 0; g < 4; g++) {
            float4 t = qptr[g];
            qp[j][2*g+0] = pack2(t.x * scale, t.y * scale);
            qp[j][2*g+1] = pack2(t.z * scale, t.w * scale);
        }
    }

    ull accp[QT][8];
#pragma unroll
    for (int j = 0; j < QT; j++)
#pragma unroll
        for (int i = 0; i < 8; i++) accp[j][i] = 0ULL;
    float mreg[QT], lreg[QT];
#pragma unroll
    for (int j = 0; j < QT; j++) { mreg[j] = -FLT_MAX; lreg[j] = 0.0f; }

    const float* kbase = kv + ((size_t)b * S) * (2 * HID) + h * DH;

    const int row = tid >> 2;   // 0..31
    const int seg = tid & 3;    // 16B segment within 64B row

    for (int t0 = start; t0 < end; t0 += TK) {
        const int tn = min(TK, end - t0);

        __syncthreads();
#pragma unroll
        for (int r = 0; r < TK; r += 32) {
            int rr = row + r;
            float4 kval = make_float4(0.f, 0.f, 0.f, 0.f);
            float4 vval = make_float4(0.f, 0.f, 0.f, 0.f);
            if (rr < tn) {
                const float* src = kbase + (size_t)(t0 + rr) * (2 * HID) + seg * 4;
                kval = *reinterpret_cast<const float4*>(src);
                vval = *reinterpret_cast<const float4*>(src + HID);
            }
            *reinterpret_cast<float4*>(Ks + rr * DH + seg * 4) = kval;
            *reinterpret_cast<float4*>(Vs + rr * DH + seg * 4) = vval;
        }
        __syncthreads();

        for (int k0 = 0; k0 < tn; k0 += KU) {
            const int nvalid = tn - k0;   // >=1 inside this loop
            float s[KU][QT];
#pragma unroll
            for (int kk = 0; kk < KU; kk++) {
                const ulonglong2* kr = reinterpret_cast<const ulonglong2*>(
                    Ks + (k0 + kk) * DH);
                ulonglong2 ka = kr[0], kb = kr[1], kc = kr[2], kd = kr[3];
#pragma unroll
                for (int j = 0; j < QT; j++) {
                    ull a = fmul2(qp[j][0], ka.x);
                    ull c = fmul2(qp[j][1], ka.y);
                    a = ffma2(qp[j][2], kb.x, a);
                    c = ffma2(qp[j][3], kb.y, c);
                    a = ffma2(qp[j][4], kc.x, a);
                    c = ffma2(qp[j][5], kc.y, c);
                    a = ffma2(qp[j][6], kd.x, a);
                    c = ffma2(qp[j][7], kd.y, c);
                    a = fadd2(a, c);
                    float lo, hi; unpack2(a, lo, hi);
                    s[kk][j] = (kk < nvalid) ? (lo + hi) : -FLT_MAX;
                }
            }

            // Online softmax per query (exp2 domain); overwrite s with p.
#pragma unroll
            for (int j = 0; j < QT; j++) {
                float cm = fmaxf(fmaxf(s[0][j], s[1][j]), fmaxf(s[2][j], s[3][j]));
                float mn = fmaxf(mreg[j], cm);
                float corr = fast_exp2(mreg[j] - mn);   // first chunk: exp2(-huge)=0
                mreg[j] = mn;
                float p0 = fast_exp2(s[0][j] - mn);
                float p1 = fast_exp2(s[1][j] - mn);
                float p2 = fast_exp2(s[2][j] - mn);
                float p3 = fast_exp2(s[3][j] - mn);
                lreg[j] = fmaf(lreg[j], corr, (p0 + p1) + (p2 + p3));
                ull cc = pack2(corr, corr);
#pragma unroll
                for (int i = 0; i < 8; i++) accp[j][i] = fmul2(cc, accp[j][i]);
                s[0][j] = p0; s[1][j] = p1; s[2][j] = p2; s[3][j] = p3;
            }

#pragma unroll
            for (int kk = 0; kk < KU; kk++) {
                const ulonglong2* vr = reinterpret_cast<const ulonglong2*>(
                    Vs + (k0 + kk) * DH);
                ulonglong2 va = vr[0], vb = vr[1], vc = vr[2], vd = vr[3];
#pragma unroll
                for (int j = 0; j < QT; j++) {
                    ull pp = pack2(s[kk][j], s[kk][j]);
                    accp[j][0] = ffma2(pp, va.x, accp[j][0]);
                    accp[j][1] = ffma2(pp, va.y, accp[j][1]);
                    accp[j][2] = ffma2(pp, vb.x, accp[j][2]);
                    accp[j][3] = ffma2(pp, vb.y, accp[j][3]);
                    accp[j][4] = ffma2(pp, vc.x, accp[j][4]);
                    accp[j][5] = ffma2(pp, vc.y, accp[j][5]);
                    accp[j][6] = ffma2(pp, vd.x, accp[j][6]);
                    accp[j][7] = ffma2(pp, vd.y, accp[j][7]);
                }
            }
        }
    }

    // Write split partials (unnormalized): m, l, acc
#pragma unroll
    for (int j = 0; j < QT; j++) {
        const int q = q0 + j * TPB;
        const int base = (b * NH + h) * S + q;
        g_m[sp * BNS + base] = mreg[j];
        g_l[sp * BNS + base] = lreg[j];
#pragma unroll
        for (int g = 0; g < 4; g++) {
            float x0, x1, x2, x3;
            unpack2(accp[j][2*g+0], x0, x1);
            unpack2(accp[j][2*g+1], x2, x3);
            g_o[(((size_t)(sp * MAXB + b) * NH + h) * 4 + g) * S + q] =
                make_float4(x0, x1, x2, x3);
        }
    }
}

__global__ __launch_bounds__(256) void mha_combine_kernel(
    float* __restrict__ out, int S, int total)   // total = B*NH*S
{
    int idx = blockIdx.x * 256 + threadIdx.x;
    if (idx >= total) return;
    const int q   = idx % S;
    const int bh  = idx / S;
    const int h   = bh % NH;
    const int b   = bh / NH;
    const int base = bh * S + q;

    float m0 = g_m[base],        l0 = g_l[base];
    float m1 = g_m[BNS + base],  l1 = g_l[BNS + base];
    float mm = fmaxf(m0, m1);
    float c0 = fast_exp2(m0 - mm);    // empty split: m=-FLT_MAX -> c=0
    float c1 = fast_exp2(m1 - mm);
    float inv = 1.0f / (l0 * c0 + l1 * c1);   // n>=1 guarantees l0>0
    float a0 = c0 * inv, a1 = c1 * inv;

    float* op = out + ((size_t)b * S + q) * HID + h * DH;
#pragma unroll
    for (int g = 0; g < 4; g++) {
        float4 o0 = g_o[(((size_t)b * NH + h) * 4 + g) * S + q];
        float4 o1 = g_o[(((size_t)(MAXB + b) * NH + h) * 4 + g) * S + q];
        reinterpret_cast<float4*>(op)[g] = make_float4(
            o0.x * a0 + o1.x * a1,
            o0.y * a0 + o1.y * a1,
            o0.z * a0 + o1.z * a1,
            o0.w * a0 + o1.w * a1);
    }
}

extern "C" void kernel_launch(void* const* d_in, const int* in_sizes, int n_in,
                              void* d_out, int out_size)
{
    const float* kv = (const float*)d_in[0];   // key_and_value [B,S,256]
    const float* qg = (const float*)d_in[1];   // query         [B,S,128]
    const int*   sl = (const int*)  d_in[2];   // seq_len       [B,1]

    const int B = in_sizes[2];                 // [B,1] ints
    const int S = in_sizes[1] / (B * HID);

    dim3 grid((S / QBLK) * NSPLIT, NH, B);
    mha_main_kernel<<<grid, TPB>>>(kv, qg, sl, S);

    const int total = B * NH * S;
    mha_combine_kernel<<<(total + 255) / 256, 256>>>((float*)d_out, S, total);
}

// round 6
// speedup vs baseline: 1.6494x; 1.3406x over previous
#include <cuda_runtime.h>
#include <cfloat>

// Problem constants (fixed by reference: HIDDEN=128, NUM_HEADS=8)
constexpr int DH   = 16;    // head dim
constexpr int NH   = 8;     // heads
constexpr int HID  = 128;   // hidden
constexpr int TPB  = 128;   // threads per block
constexpr int QT   = 2;     // queries per thread
constexpr int QBLK = TPB * QT;  // 256 queries per block
constexpr int TK   = 128;   // key tile staged in smem
constexpr int KU   = 8;     // key unroll inside tile
constexpr int NSPLIT = 4;   // key-range splits (flash split-K)

// Dataset-fixed max shapes (B=4, S=2048) for static scratch.
constexpr int MAXB = 4;
constexpr int MAXS = 2048;
constexpr int BNS  = MAXB * NH * MAXS;

// Split-K partials: m (log2-domain running max), l (running denom),
// unnormalized accumulator o ([split][b][h][g][q] float4 groups, coalesced on q).
__device__ float  g_m[NSPLIT * BNS];
__device__ float  g_l[NSPLIT * BNS];
__device__ float4 g_o[NSPLIT * MAXB * NH * 4 * MAXS];

typedef unsigned long long ull;

__device__ __forceinline__ float fast_exp2(float x) {
    float r; asm("ex2.approx.ftz.f32 %0, %1;" : "=f"(r) : "f"(x)); return r;
}
__device__ __forceinline__ ull pack2(float lo, float hi) {
    ull r; asm("mov.b64 %0, {%1, %2};" : "=l"(r) : "f"(lo), "f"(hi)); return r;
}
__device__ __forceinline__ void unpack2(ull v, float& lo, float& hi) {
    asm("mov.b64 {%0, %1}, %2;" : "=f"(lo), "=f"(hi) : "l"(v));
}
// Packed 2x fp32 ops (PTX ISA 8.6, sm_100+; IEEE rn per lane)
__device__ __forceinline__ ull ffma2(ull a, ull b, ull c) {
    ull r; asm("fma.rn.f32x2 %0, %1, %2, %3;" : "=l"(r) : "l"(a), "l"(b), "l"(c)); return r;
}
__device__ __forceinline__ ull fmul2(ull a, ull b) {
    ull r; asm("mul.rn.f32x2 %0, %1, %2;" : "=l"(r) : "l"(a), "l"(b)); return r;
}
__device__ __forceinline__ ull fadd2(ull a, ull b) {
    ull r; asm("add.rn.f32x2 %0, %1, %2;" : "=l"(r) : "l"(a), "l"(b)); return r;
}

// One KU-key chunk: dot products (optionally masked), online softmax, V accum.
#define MHA_CHUNK(K0, MASKED)                                                  \
do {                                                                           \
    const int nvalid = tn - (K0);                                              \
    float s[KU][QT];                                                           \
    _Pragma("unroll")                                                          \
    for (int kk = 0; kk < KU; kk++) {                                          \
        const ulonglong2* kr = reinterpret_cast<const ulonglong2*>(            \
            Ks + ((K0) + kk) * DH);                                            \
        ulonglong2 ka = kr[0], kb = kr[1], kc = kr[2], kd = kr[3];             \
        _Pragma("unroll")                                                      \
        for (int j = 0; j < QT; j++) {                                         \
            ull a = fmul2(qp[j][0], ka.x);                                     \
            ull c = fmul2(qp[j][1], ka.y);                                     \
            a = ffma2(qp[j][2], kb.x, a);                                      \
            c = ffma2(qp[j][3], kb.y, c);                                      \
            a = ffma2(qp[j][4], kc.x, a);                                      \
            c = ffma2(qp[j][5], kc.y, c);                                      \
            a = ffma2(qp[j][6], kd.x, a);                                      \
            c = ffma2(qp[j][7], kd.y, c);                                      \
            a = fadd2(a, c);                                                   \
            float lo, hi; unpack2(a, lo, hi);                                  \
            float sv = lo + hi;                                                \
            s[kk][j] = ((MASKED) && kk >= nvalid) ? -FLT_MAX : sv;             \
        }                                                                      \
    }                                                                          \
    _Pragma("unroll")                                                          \
    for (int j = 0; j < QT; j++) {                                             \
        float cm = fmaxf(fmaxf(fmaxf(s[0][j], s[1][j]), fmaxf(s[2][j], s[3][j])), \
                         fmaxf(fmaxf(s[4][j], s[5][j]), fmaxf(s[6][j], s[7][j]))); \
        float mn = fmaxf(mreg[j], cm);                                         \
        float corr = fast_exp2(mreg[j] - mn);                                  \
        mreg[j] = mn;                                                          \
        float p0 = fast_exp2(s[0][j] - mn);                                    \
        float p1 = fast_exp2(s[1][j] - mn);                                    \
        float p2 = fast_exp2(s[2][j] - mn);                                    \
        float p3 = fast_exp2(s[3][j] - mn);                                    \
        float p4 = fast_exp2(s[4][j] - mn);                                    \
        float p5 = fast_exp2(s[5][j] - mn);                                    \
        float p6 = fast_exp2(s[6][j] - mn);                                    \
        float p7 = fast_exp2(s[7][j] - mn);                                    \
        float psum = ((p0 + p1) + (p2 + p3)) + ((p4 + p5) + (p6 + p7));        \
        lreg[j] = fmaf(lreg[j], corr, psum);                                   \
        ull cc = pack2(corr, corr);                                            \
        _Pragma("unroll")                                                      \
        for (int i = 0; i < 8; i++) accp[j][i] = fmul2(cc, accp[j][i]);        \
        s[0][j]=p0; s[1][j]=p1; s[2][j]=p2; s[3][j]=p3;                        \
        s[4][j]=p4; s[5][j]=p5; s[6][j]=p6; s[7][j]=p7;                        \
    }                                                                          \
    _Pragma("unroll")                                                          \
    for (int kk = 0; kk < KU; kk++) {                                          \
        const ulonglong2* vr = reinterpret_cast<const ulonglong2*>(            \
            Vs + ((K0) + kk) * DH);                                            \
        ulonglong2 va = vr[0], vb = vr[1], vc = vr[2], vd = vr[3];             \
        _Pragma("unroll")                                                      \
        for (int j = 0; j < QT; j++) {                                         \
            ull pp = pack2(s[kk][j], s[kk][j]);                                \
            accp[j][0] = ffma2(pp, va.x, accp[j][0]);                          \
            accp[j][1] = ffma2(pp, va.y, accp[j][1]);                          \
            accp[j][2] = ffma2(pp, vb.x, accp[j][2]);                          \
            accp[j][3] = ffma2(pp, vb.y, accp[j][3]);                          \
            accp[j][4] = ffma2(pp, vc.x, accp[j][4]);                          \
            accp[j][5] = ffma2(pp, vc.y, accp[j][5]);                          \
            accp[j][6] = ffma2(pp, vd.x, accp[j][6]);                          \
            accp[j][7] = ffma2(pp, vd.y, accp[j][7]);                          \
        }                                                                      \
    }                                                                          \
} while (0)

__global__ __launch_bounds__(TPB) void mha_main_kernel(
    const float* __restrict__ kv,     // [B, S, 2*HID]
    const float* __restrict__ qg,     // [B, S, HID]
    const int*   __restrict__ slen,   // [B]
    int S)
{
    __shared__ float Ks[TK * DH];
    __shared__ float Vs[TK * DH];

    const int b  = blockIdx.z;
    const int h  = blockIdx.y;
    const int qb = blockIdx.x / NSPLIT;
    const int sp = blockIdx.x % NSPLIT;
    const int n  = slen[b];

    // Balanced key range for this split: chunk = ceil(n/NSPLIT)
    const int chunk = (n + NSPLIT - 1) / NSPLIT;
    const int start = sp * chunk;
    const int end   = min(n, start + chunk);

    const int tid = threadIdx.x;
    const int q0  = qb * QBLK + tid;          // query 0; query 1 = q0 + TPB

    // Fold sqrt(d_head)=4 (reference MULTIPLIES by sqrt) and log2(e) into q.
    const float scale = 4.0f * 1.4426950408889634f;

    // Packed q for both queries: qp[j][i] = (q[2i], q[2i+1])
    ull qp[QT][8];
#pragma unroll
    for (int j = 0; j < QT; j++) {
        const float4* qptr = reinterpret_cast<const float4*>(
            qg + ((size_t)b * S + (q0 + j * TPB)) * HID + h * DH);
#pragma unroll
        for (int g = 0; g < 4; g++) {
            float4 t = qptr[g];
            qp[j][2*g+0] = pack2(t.x * scale, t.y * scale);
            qp[j][2*g+1] = pack2(t.z * scale, t.w * scale);
        }
    }

    ull accp[QT][8];
#pragma unroll
    for (int j = 0; j < QT; j++)
#pragma unroll
        for (int i = 0; i < 8; i++) accp[j][i] = 0ULL;
    float mreg[QT], lreg[QT];
#pragma unroll
    for (int j = 0; j < QT; j++) { mreg[j] = -FLT_MAX; lreg[j] = 0.0f; }

    const float* kbase = kv + ((size_t)b * S) * (2 * HID) + h * DH;

    const int row = tid >> 2;   // 0..31
    const int seg = tid & 3;    // 16B segment within 64B row

    for (int t0 = start; t0 < end; t0 += TK) {
        const int tn = min(TK, end - t0);

        __syncthreads();
#pragma unroll
        for (int r = 0; r < TK; r += 32) {
            int rr = row + r;
            float4 kval = make_float4(0.f, 0.f, 0.f, 0.f);
            float4 vval = make_float4(0.f, 0.f, 0.f, 0.f);
            if (rr < tn) {
                const float* src = kbase + (size_t)(t0 + rr) * (2 * HID) + seg * 4;
                kval = *reinterpret_cast<const float4*>(src);
                vval = *reinterpret_cast<const float4*>(src + HID);
            }
            *reinterpret_cast<float4*>(Ks + rr * DH + seg * 4) = kval;
            *reinterpret_cast<float4*>(Vs + rr * DH + seg * 4) = vval;
        }
        __syncthreads();

        // Fast path: full KU-key chunks (no masking). Tail chunk masked.
        const int full = tn & ~(KU - 1);
        int k0 = 0;
        for (; k0 < full; k0 += KU) {
            MHA_CHUNK(k0, 0);
        }
        if (k0 < tn) {
            MHA_CHUNK(k0, 1);
        }
    }

    // Write split partials (unnormalized): m, l, acc
#pragma unroll
    for (int j = 0; j < QT; j++) {
        const int q = q0 + j * TPB;
        const int base = (b * NH + h) * S + q;
        g_m[sp * BNS + base] = mreg[j];
        g_l[sp * BNS + base] = lreg[j];
#pragma unroll
        for (int g = 0; g < 4; g++) {
            float x0, x1, x2, x3;
            unpack2(accp[j][2*g+0], x0, x1);
            unpack2(accp[j][2*g+1], x2, x3);
            g_o[(((size_t)(sp * MAXB + b) * NH + h) * 4 + g) * S + q] =
                make_float4(x0, x1, x2, x3);
        }
    }
}

__global__ __launch_bounds__(256) void mha_combine_kernel(
    float* __restrict__ out, int S, int total)   // total = B*NH*S
{
    int idx = blockIdx.x * 256 + threadIdx.x;
    if (idx >= total) return;
    const int q   = idx % S;
    const int bh  = idx / S;
    const int h   = bh % NH;
    const int b   = bh / NH;
    const int base = bh * S + q;

    float m[NSPLIT], l[NSPLIT];
    float mm = -FLT_MAX;
#pragma unroll
    for (int sp = 0; sp < NSPLIT; sp++) {
        m[sp] = g_m[sp * BNS + base];
        l[sp] = g_l[sp * BNS + base];
        mm = fmaxf(mm, m[sp]);
    }
    float c[NSPLIT];
    float denom = 0.0f;
#pragma unroll
    for (int sp = 0; sp < NSPLIT; sp++) {
        c[sp] = fast_exp2(m[sp] - mm);    // empty split: m=-FLT_MAX -> c=0
        denom = fmaf(l[sp], c[sp], denom);
    }
    float inv = 1.0f / denom;             // n>=1 guarantees split-0 l>0

    float* op = out + ((size_t)b * S + q) * HID + h * DH;
#pragma unroll
    for (int g = 0; g < 4; g++) {
        float4 acc = make_float4(0.f, 0.f, 0.f, 0.f);
#pragma unroll
        for (int sp = 0; sp < NSPLIT; sp++) {
            float a = c[sp] * inv;
            float4 o = g_o[(((size_t)(sp * MAXB + b) * NH + h) * 4 + g) * S + q];
            acc.x = fmaf(o.x, a, acc.x);
            acc.y = fmaf(o.y, a, acc.y);
            acc.z = fmaf(o.z, a, acc.z);
            acc.w = fmaf(o.w, a, acc.w);
        }
        reinterpret_cast<float4*>(op)[g] = acc;
    }
}

extern "C" void kernel_launch(void* const* d_in, const int* in_sizes, int n_in,
                              void* d_out, int out_size)
{
    const float* kv = (const float*)d_in[0];   // key_and_value [B,S,256]
    const float* qg = (const float*)d_in[1];   // query         [B,S,128]
    const int*   sl = (const int*)  d_in[2];   // seq_len       [B,1]

    const int B = in_sizes[2];                 // [B,1] ints
    const int S = in_sizes[1] / (B * HID);

    dim3 grid((S / QBLK) * NSPLIT, NH, B);
    mha_main_kernel<<<grid, TPB>>>(kv, qg, sl, S);

    const int total = B * NH * S;
    mha_combine_kernel<<<(total + 255) / 256, 256>>>((float*)d_out, S, total);
}